// round 16
// baseline (speedup 1.0000x reference)
#include <cuda_runtime.h>
#include <cuda_fp16.h>

__device__ float g_rpb[6 * 225];
#define QK_SCALE 0.17677669529663687f

static __device__ __forceinline__ unsigned smem_u32(const void *p) {
    unsigned a;
    asm("{ .reg .u64 t; cvta.to.shared.u64 t, %1; cvt.u32.u64 %0, t; }" : "=r"(a) : "l"(p));
    return a;
}
static __device__ __forceinline__ unsigned pkh2(float lo, float hi) {
    unsigned r;
    asm("cvt.rn.f16x2.f32 %0, %1, %2;" : "=r"(r) : "f"(hi), "f"(lo));
    return r;
}
static __device__ __forceinline__ uint4 ldm4(unsigned addr) {
    uint4 r;
    asm volatile("ldmatrix.sync.aligned.m8n8.x4.shared.b16 {%0,%1,%2,%3}, [%4];"
                 : "=r"(r.x), "=r"(r.y), "=r"(r.z), "=r"(r.w) : "r"(addr));
    return r;
}
static __device__ __forceinline__ uint4 ldm4t(unsigned addr) {
    uint4 r;
    asm volatile("ldmatrix.sync.aligned.m8n8.x4.trans.shared.b16 {%0,%1,%2,%3}, [%4];"
                 : "=r"(r.x), "=r"(r.y), "=r"(r.z), "=r"(r.w) : "r"(addr));
    return r;
}
static __device__ __forceinline__ void mmaf16(float *c, uint4 a, unsigned b0, unsigned b1) {
    asm volatile("mma.sync.aligned.m16n8k16.row.col.f32.f16.f16.f32 "
                 "{%0,%1,%2,%3}, {%4,%5,%6,%7}, {%8,%9}, {%0,%1,%2,%3};"
                 : "+f"(c[0]), "+f"(c[1]), "+f"(c[2]), "+f"(c[3])
                 : "r"(a.x), "r"(a.y), "r"(a.z), "r"(a.w), "r"(b0), "r"(b1));
}

static __device__ __forceinline__ void ln_relu12(float *x, const float *g, const float *b) {
    float m = 0.f;
#pragma unroll
    for (int j = 0; j < 12; j++) m += x[j];
    m *= (1.0f / 12.0f);
    float v = 0.f;
#pragma unroll
    for (int j = 0; j < 12; j++) { float d = x[j] - m; v += d * d; }
    v *= (1.0f / 12.0f);
    float inv = rsqrtf(v + 1e-5f);
#pragma unroll
    for (int j = 0; j < 12; j++) x[j] = fmaxf((x[j] - m) * inv * g[j] + b[j], 0.f);
}

__global__ void rpe_mlp_kernel(const float *__restrict__ w_proj, const float *__restrict__ b_proj,
                               const float *__restrict__ ln1_g, const float *__restrict__ ln1_b,
                               const float *__restrict__ w1,    const float *__restrict__ b1,
                               const float *__restrict__ ln2_g, const float *__restrict__ ln2_b,
                               const float *__restrict__ w2,    const float *__restrict__ b2,
                               const float *__restrict__ ln3_g, const float *__restrict__ ln3_b,
                               const float *__restrict__ w3,    const float *__restrict__ b3) {
    int r = threadIdx.x;
    if (r >= 225) return;
    float in0 = (float)(r / 15 - 7), in1 = (float)(r % 15 - 7);
    float x[12], y[12];
#pragma unroll
    for (int j = 0; j < 12; j++) x[j] = in0 * w_proj[j] + in1 * w_proj[12 + j] + b_proj[j];
    ln_relu12(x, ln1_g, ln1_b);
#pragma unroll
    for (int j = 0; j < 12; j++) {
        float a = b1[j];
#pragma unroll
        for (int i = 0; i < 12; i++) a += x[i] * w1[i * 12 + j];
        y[j] = a;
    }
    ln_relu12(y, ln2_g, ln2_b);
#pragma unroll
    for (int j = 0; j < 12; j++) {
        float a = b2[j];
#pragma unroll
        for (int i = 0; i < 12; i++) a += y[i] * w2[i * 12 + j];
        x[j] = a;
    }
    ln_relu12(x, ln3_g, ln3_b);
#pragma unroll
    for (int h = 0; h < 6; h++) {
        float a = b3[h];
#pragma unroll
        for (int i = 0; i < 12; i++) a += x[i] * w3[i * 6 + h];
        g_rpb[h * 225 + r] = a;
    }
}

// smem layout: fp16, 64 rows x 64B (16 u32), 16B unit u at phys (u ^ ((row>>1)&3)).
// -> ldmatrix 8-row phases hit (4*row + u^((row>>1)&3)) mod 8 = all-distinct slots: conflict-free.
static __device__ __forceinline__ unsigned swadr(unsigned base, int row, int u) {
    return base + row * 64 + ((u ^ ((row >> 1) & 3)) << 4);
}

// CTA = (window, head); 128 threads / 4 warps; warp w owns S rows 16w..16w+15.
// launch_bounds(128, 8): cap regs at 64 -> 8 CTAs/SM -> 32 warps/SM for HBM saturation.
__global__ __launch_bounds__(128, 8) void attn_kernel(const float *__restrict__ Q,
                                                      const float *__restrict__ K,
                                                      const float *__restrict__ V,
                                                      float *__restrict__ O) {
    __shared__ __align__(16) unsigned uQ[64 * 16];
    __shared__ __align__(16) unsigned uK[64 * 16];
    __shared__ __align__(16) unsigned uV[64 * 16];
    __shared__ float srpb[228];

    int head = blockIdx.x % 6, win = blockIdx.x / 6;
    int b = win >> 10, whb = (win >> 5) & 31, wwb = win & 31;
    int tid = threadIdx.x, lane = tid & 31, w = tid >> 5;

    int base = b * (65536 * 192) + head * 32;     // 32-bit offsets (max < 2^26 floats)
    int r0 = whb << 3, c0 = wwb << 3;

    // ---- load f32->f16 smem: LDG.128, STS.64 into swizzled layout ----
    int cq = lane & 7;       // 16B chunk (4 channels)
    int psub = lane >> 3;    // pixel-within-group
#pragma unroll
    for (int i = 0; i < 4; i++) {
        int p = 16 * w + 4 * i + psub;
        int g = base + ((r0 + (p >> 3)) * 256 + c0 + (p & 7)) * 192 + cq * 4;
        float4 fq = *reinterpret_cast<const float4 *>(Q + g);
        float4 fk = *reinterpret_cast<const float4 *>(K + g);
        float4 fv = *reinterpret_cast<const float4 *>(V + g);
        int off = p * 16 + (((cq >> 1) ^ ((p >> 1) & 3)) << 2) + (cq & 1) * 2;
        *reinterpret_cast<uint2 *>(uQ + off) =
            make_uint2(pkh2(fq.x * QK_SCALE, fq.y * QK_SCALE), pkh2(fq.z * QK_SCALE, fq.w * QK_SCALE));
        *reinterpret_cast<uint2 *>(uK + off) = make_uint2(pkh2(fk.x, fk.y), pkh2(fk.z, fk.w));
        *reinterpret_cast<uint2 *>(uV + off) = make_uint2(pkh2(fv.x, fv.y), pkh2(fv.z, fv.w));
    }
    for (int i = tid; i < 225; i += 128) srpb[i] = g_rpb[head * 225 + i];
    __syncthreads();

    unsigned bQ = smem_u32(uQ), bK = smem_u32(uK), bV = smem_u32(uV);

    // ---- S = Q K^T : m16 x n64, k32 ----
    float c[8][4];
#pragma unroll
    for (int t = 0; t < 8; t++) { c[t][0] = 0.f; c[t][1] = 0.f; c[t][2] = 0.f; c[t][3] = 0.f; }
#pragma unroll
    for (int kk = 0; kk < 2; kk++) {
        int uu = kk * 2 + (lane >> 4);
        uint4 a = ldm4(swadr(bQ, 16 * w + (lane & 15), uu));
#pragma unroll
        for (int nb = 0; nb < 4; nb++) {
            uint4 kf = ldm4(swadr(bK, 16 * nb + (lane & 15), uu));
            mmaf16(c[2 * nb],     a, kf.x, kf.z);
            mmaf16(c[2 * nb + 1], a, kf.y, kf.w);
        }
    }

    // ---- + rpb ----
    int j2 = (lane & 3) * 2, e = lane >> 2;
    int djA = e + 7 - j2;
#pragma unroll
    for (int t = 0; t < 8; t++) {
        int di0 = (2 * w + 7 - t) * 15;
        c[t][0] += srpb[di0 + djA];
        c[t][1] += srpb[di0 + djA - 1];
        c[t][2] += srpb[di0 + 15 + djA];
        c[t][3] += srpb[di0 + 15 + djA - 1];
    }

    // ---- softmax (rows e0 = 16w+e and e1 = e0+8), quad shfl reductions ----
    float mx0 = c[0][0], mx1 = c[0][2];
#pragma unroll
    for (int t = 0; t < 8; t++) {
        mx0 = fmaxf(mx0, fmaxf(c[t][0], c[t][1]));
        mx1 = fmaxf(mx1, fmaxf(c[t][2], c[t][3]));
    }
    mx0 = fmaxf(mx0, __shfl_xor_sync(0xffffffffu, mx0, 1));
    mx0 = fmaxf(mx0, __shfl_xor_sync(0xffffffffu, mx0, 2));
    mx1 = fmaxf(mx1, __shfl_xor_sync(0xffffffffu, mx1, 1));
    mx1 = fmaxf(mx1, __shfl_xor_sync(0xffffffffu, mx1, 2));
    float s0 = 0.f, s1 = 0.f;
#pragma unroll
    for (int t = 0; t < 8; t++) {
        c[t][0] = __expf(c[t][0] - mx0); s0 += c[t][0];
        c[t][1] = __expf(c[t][1] - mx0); s0 += c[t][1];
        c[t][2] = __expf(c[t][2] - mx1); s1 += c[t][2];
        c[t][3] = __expf(c[t][3] - mx1); s1 += c[t][3];
    }
    s0 += __shfl_xor_sync(0xffffffffu, s0, 1);
    s0 += __shfl_xor_sync(0xffffffffu, s0, 2);
    s1 += __shfl_xor_sync(0xffffffffu, s1, 1);
    s1 += __shfl_xor_sync(0xffffffffu, s1, 2);
    float inv0 = 1.0f / s0, inv1 = 1.0f / s1;

    // ---- O = P V : P stays in registers (C-frag == A-frag layout) ----
    float co[4][4];
#pragma unroll
    for (int t = 0; t < 4; t++) { co[t][0] = 0.f; co[t][1] = 0.f; co[t][2] = 0.f; co[t][3] = 0.f; }
#pragma unroll
    for (int K2 = 0; K2 < 4; K2++) {
        uint4 a;
        a.x = pkh2(c[2 * K2][0],     c[2 * K2][1]);
        a.y = pkh2(c[2 * K2][2],     c[2 * K2][3]);
        a.z = pkh2(c[2 * K2 + 1][0], c[2 * K2 + 1][1]);
        a.w = pkh2(c[2 * K2 + 1][2], c[2 * K2 + 1][3]);
        int rowv = 16 * K2 + (lane & 7) + ((lane >> 4) & 1) * 8;
#pragma unroll
        for (int nb2 = 0; nb2 < 2; nb2++) {
            uint4 vf = ldm4t(swadr(bV, rowv, nb2 * 2 + ((lane >> 3) & 1)));
            mmaf16(co[2 * nb2],     a, vf.x, vf.z);
            mmaf16(co[2 * nb2 + 1], a, vf.y, vf.w);
        }
    }

    // ---- epilogue: normalize + direct STG.64 (full 32B sectors per quad) ----
#pragma unroll
    for (int t = 0; t < 4; t++) {
        int ch = 8 * t + j2;
        int g0 = base + ((r0 + 2 * w) * 256 + c0 + e) * 192 + ch;
        int g1 = base + ((r0 + 2 * w + 1) * 256 + c0 + e) * 192 + ch;
        *reinterpret_cast<float2 *>(O + g0) = make_float2(co[t][0] * inv0, co[t][1] * inv0);
        *reinterpret_cast<float2 *>(O + g1) = make_float2(co[t][2] * inv1, co[t][3] * inv1);
    }
}

extern "C" void kernel_launch(void *const *d_in, const int *in_sizes, int n_in,
                              void *d_out, int out_size) {
    const float *q = (const float *)d_in[0];
    const float *k = (const float *)d_in[1];
    const float *v = (const float *)d_in[2];
    rpe_mlp_kernel<<<1, 256>>>((const float *)d_in[5], (const float *)d_in[6],
                               (const float *)d_in[7], (const float *)d_in[8],
                               (const float *)d_in[9], (const float *)d_in[10],
                               (const float *)d_in[11], (const float *)d_in[12],
                               (const float *)d_in[13], (const float *)d_in[14],
                               (const float *)d_in[15], (const float *)d_in[16],
                               (const float *)d_in[17], (const float *)d_in[18]);
    attn_kernel<<<24576, 128>>>(q, k, v, (float *)d_out);
}

// round 17
// speedup vs baseline: 1.0387x; 1.0387x over previous
#include <cuda_runtime.h>
#include <cuda_fp16.h>

__device__ float g_rpb[6 * 225];
#define QK_SCALE 0.17677669529663687f

static __device__ __forceinline__ unsigned smem_u32(const void *p) {
    unsigned a;
    asm("{ .reg .u64 t; cvta.to.shared.u64 t, %1; cvt.u32.u64 %0, t; }" : "=r"(a) : "l"(p));
    return a;
}
static __device__ __forceinline__ unsigned pkh2(float lo, float hi) {
    unsigned r;
    asm("cvt.rn.f16x2.f32 %0, %1, %2;" : "=r"(r) : "f"(hi), "f"(lo));
    return r;
}
static __device__ __forceinline__ uint4 ldm4(unsigned addr) {
    uint4 r;
    asm volatile("ldmatrix.sync.aligned.m8n8.x4.shared.b16 {%0,%1,%2,%3}, [%4];"
                 : "=r"(r.x), "=r"(r.y), "=r"(r.z), "=r"(r.w) : "r"(addr));
    return r;
}
static __device__ __forceinline__ uint4 ldm4t(unsigned addr) {
    uint4 r;
    asm volatile("ldmatrix.sync.aligned.m8n8.x4.trans.shared.b16 {%0,%1,%2,%3}, [%4];"
                 : "=r"(r.x), "=r"(r.y), "=r"(r.z), "=r"(r.w) : "r"(addr));
    return r;
}
static __device__ __forceinline__ void mmaf16(float *c, uint4 a, unsigned b0, unsigned b1) {
    asm volatile("mma.sync.aligned.m16n8k16.row.col.f32.f16.f16.f32 "
                 "{%0,%1,%2,%3}, {%4,%5,%6,%7}, {%8,%9}, {%0,%1,%2,%3};"
                 : "+f"(c[0]), "+f"(c[1]), "+f"(c[2]), "+f"(c[3])
                 : "r"(a.x), "r"(a.y), "r"(a.z), "r"(a.w), "r"(b0), "r"(b1));
}

static __device__ __forceinline__ void ln_relu12(float *x, const float *g, const float *b) {
    float m = 0.f;
#pragma unroll
    for (int j = 0; j < 12; j++) m += x[j];
    m *= (1.0f / 12.0f);
    float v = 0.f;
#pragma unroll
    for (int j = 0; j < 12; j++) { float d = x[j] - m; v += d * d; }
    v *= (1.0f / 12.0f);
    float inv = rsqrtf(v + 1e-5f);
#pragma unroll
    for (int j = 0; j < 12; j++) x[j] = fmaxf((x[j] - m) * inv * g[j] + b[j], 0.f);
}

__global__ void rpe_mlp_kernel(const float *__restrict__ w_proj, const float *__restrict__ b_proj,
                               const float *__restrict__ ln1_g, const float *__restrict__ ln1_b,
                               const float *__restrict__ w1,    const float *__restrict__ b1,
                               const float *__restrict__ ln2_g, const float *__restrict__ ln2_b,
                               const float *__restrict__ w2,    const float *__restrict__ b2,
                               const float *__restrict__ ln3_g, const float *__restrict__ ln3_b,
                               const float *__restrict__ w3,    const float *__restrict__ b3) {
    // Dependent attn CTAs may launch immediately; they griddepcontrol.wait before reading g_rpb.
    asm volatile("griddepcontrol.launch_dependents;");
    int r = threadIdx.x;
    if (r >= 225) return;
    float in0 = (float)(r / 15 - 7), in1 = (float)(r % 15 - 7);
    float x[12], y[12];
#pragma unroll
    for (int j = 0; j < 12; j++) x[j] = in0 * w_proj[j] + in1 * w_proj[12 + j] + b_proj[j];
    ln_relu12(x, ln1_g, ln1_b);
#pragma unroll
    for (int j = 0; j < 12; j++) {
        float a = b1[j];
#pragma unroll
        for (int i = 0; i < 12; i++) a += x[i] * w1[i * 12 + j];
        y[j] = a;
    }
    ln_relu12(y, ln2_g, ln2_b);
#pragma unroll
    for (int j = 0; j < 12; j++) {
        float a = b2[j];
#pragma unroll
        for (int i = 0; i < 12; i++) a += y[i] * w2[i * 12 + j];
        x[j] = a;
    }
    ln_relu12(x, ln3_g, ln3_b);
#pragma unroll
    for (int h = 0; h < 6; h++) {
        float a = b3[h];
#pragma unroll
        for (int i = 0; i < 12; i++) a += x[i] * w3[i * 6 + h];
        g_rpb[h * 225 + r] = a;
    }
}

// smem layout: fp16, 64 rows x 64B (16 u32), 16B unit u at phys (u ^ ((row>>1)&3)).
// -> ldmatrix 8-row phases hit (4*row + u^((row>>1)&3)) mod 8 = all-distinct slots: conflict-free.
static __device__ __forceinline__ unsigned swadr(unsigned base, int row, int u) {
    return base + row * 64 + ((u ^ ((row >> 1) & 3)) << 4);
}

// CTA = (window, head); 128 threads / 4 warps; warp w owns S rows 16w..16w+15.
__global__ __launch_bounds__(128, 8) void attn_kernel(const float *__restrict__ Q,
                                                      const float *__restrict__ K,
                                                      const float *__restrict__ V,
                                                      float *__restrict__ O) {
    __shared__ __align__(16) unsigned uQ[64 * 16];
    __shared__ __align__(16) unsigned uK[64 * 16];
    __shared__ __align__(16) unsigned uV[64 * 16];
    __shared__ float srpb[228];

    int head = blockIdx.x % 6, win = blockIdx.x / 6;
    int b = win >> 10, whb = (win >> 5) & 31, wwb = win & 31;
    int tid = threadIdx.x, lane = tid & 31, w = tid >> 5;

    int base = b * (65536 * 192) + head * 32;     // 32-bit offsets
    int r0 = whb << 3, c0 = wwb << 3;

    // ---- load f32->f16 smem: LDG.128 (streaming), STS.64 swizzled ----
    int cq = lane & 7;       // 16B chunk (4 channels)
    int psub = lane >> 3;    // pixel-within-group
    // g(i) = G0 + (i>>1)*49152 + (i&1)*768
    int G0 = base + ((r0 + 2 * w) * 256 + c0 + psub) * 192 + cq * 4;
#pragma unroll
    for (int i = 0; i < 4; i++) {
        int p = 16 * w + 4 * i + psub;
        int g = G0 + (i >> 1) * 49152 + (i & 1) * 768;
        float4 fq = __ldcs(reinterpret_cast<const float4 *>(Q + g));
        float4 fk = __ldcs(reinterpret_cast<const float4 *>(K + g));
        float4 fv = __ldcs(reinterpret_cast<const float4 *>(V + g));
        int off = p * 16 + (((cq >> 1) ^ ((p >> 1) & 3)) << 2) + (cq & 1) * 2;
        *reinterpret_cast<uint2 *>(uQ + off) =
            make_uint2(pkh2(fq.x * QK_SCALE, fq.y * QK_SCALE), pkh2(fq.z * QK_SCALE, fq.w * QK_SCALE));
        *reinterpret_cast<uint2 *>(uK + off) = make_uint2(pkh2(fk.x, fk.y), pkh2(fk.z, fk.w));
        *reinterpret_cast<uint2 *>(uV + off) = make_uint2(pkh2(fv.x, fv.y), pkh2(fv.z, fv.w));
    }
    // rpb produced by the PDL-overlapped rpe kernel: wait only now.
    asm volatile("griddepcontrol.wait;" ::: "memory");
    for (int i = tid; i < 225; i += 128) srpb[i] = g_rpb[head * 225 + i];
    __syncthreads();

    unsigned bQ = smem_u32(uQ), bK = smem_u32(uK), bV = smem_u32(uV);

    // ---- S = Q K^T : m16 x n64, k32 ----
    float c[8][4];
#pragma unroll
    for (int t = 0; t < 8; t++) { c[t][0] = 0.f; c[t][1] = 0.f; c[t][2] = 0.f; c[t][3] = 0.f; }
#pragma unroll
    for (int kk = 0; kk < 2; kk++) {
        int uu = kk * 2 + (lane >> 4);
        uint4 a = ldm4(swadr(bQ, 16 * w + (lane & 15), uu));
#pragma unroll
        for (int nb = 0; nb < 4; nb++) {
            uint4 kf = ldm4(swadr(bK, 16 * nb + (lane & 15), uu));
            mmaf16(c[2 * nb],     a, kf.x, kf.z);
            mmaf16(c[2 * nb + 1], a, kf.y, kf.w);
        }
    }

    // ---- + rpb ----
    int j2 = (lane & 3) * 2, e = lane >> 2;
    int djA = e + 7 - j2;
#pragma unroll
    for (int t = 0; t < 8; t++) {
        int di0 = (2 * w + 7 - t) * 15;
        c[t][0] += srpb[di0 + djA];
        c[t][1] += srpb[di0 + djA - 1];
        c[t][2] += srpb[di0 + 15 + djA];
        c[t][3] += srpb[di0 + 15 + djA - 1];
    }

    // ---- softmax (rows e0 = 16w+e and e1 = e0+8), quad shfl reductions ----
    float mx0 = c[0][0], mx1 = c[0][2];
#pragma unroll
    for (int t = 0; t < 8; t++) {
        mx0 = fmaxf(mx0, fmaxf(c[t][0], c[t][1]));
        mx1 = fmaxf(mx1, fmaxf(c[t][2], c[t][3]));
    }
    mx0 = fmaxf(mx0, __shfl_xor_sync(0xffffffffu, mx0, 1));
    mx0 = fmaxf(mx0, __shfl_xor_sync(0xffffffffu, mx0, 2));
    mx1 = fmaxf(mx1, __shfl_xor_sync(0xffffffffu, mx1, 1));
    mx1 = fmaxf(mx1, __shfl_xor_sync(0xffffffffu, mx1, 2));
    float s0 = 0.f, s1 = 0.f;
#pragma unroll
    for (int t = 0; t < 8; t++) {
        c[t][0] = __expf(c[t][0] - mx0); s0 += c[t][0];
        c[t][1] = __expf(c[t][1] - mx0); s0 += c[t][1];
        c[t][2] = __expf(c[t][2] - mx1); s1 += c[t][2];
        c[t][3] = __expf(c[t][3] - mx1); s1 += c[t][3];
    }
    s0 += __shfl_xor_sync(0xffffffffu, s0, 1);
    s0 += __shfl_xor_sync(0xffffffffu, s0, 2);
    s1 += __shfl_xor_sync(0xffffffffu, s1, 1);
    s1 += __shfl_xor_sync(0xffffffffu, s1, 2);
    float inv0 = 1.0f / s0, inv1 = 1.0f / s1;

    // ---- O = P V : P stays in registers (C-frag == A-frag layout) ----
    float co[4][4];
#pragma unroll
    for (int t = 0; t < 4; t++) { co[t][0] = 0.f; co[t][1] = 0.f; co[t][2] = 0.f; co[t][3] = 0.f; }
#pragma unroll
    for (int K2 = 0; K2 < 4; K2++) {
        uint4 a;
        a.x = pkh2(c[2 * K2][0],     c[2 * K2][1]);
        a.y = pkh2(c[2 * K2][2],     c[2 * K2][3]);
        a.z = pkh2(c[2 * K2 + 1][0], c[2 * K2 + 1][1]);
        a.w = pkh2(c[2 * K2 + 1][2], c[2 * K2 + 1][3]);
        int rowv = 16 * K2 + (lane & 7) + ((lane >> 4) & 1) * 8;
#pragma unroll
        for (int nb2 = 0; nb2 < 2; nb2++) {
            uint4 vf = ldm4t(swadr(bV, rowv, nb2 * 2 + ((lane >> 3) & 1)));
            mmaf16(co[2 * nb2],     a, vf.x, vf.z);
            mmaf16(co[2 * nb2 + 1], a, vf.y, vf.w);
        }
    }

    // ---- epilogue: normalize + streaming STG.64 ----
    int gE = base + ((r0 + 2 * w) * 256 + c0 + e) * 192 + j2;
#pragma unroll
    for (int t = 0; t < 4; t++) {
        __stcs(reinterpret_cast<float2 *>(O + gE + 8 * t),
               make_float2(co[t][0] * inv0, co[t][1] * inv0));
        __stcs(reinterpret_cast<float2 *>(O + gE + 49152 + 8 * t),
               make_float2(co[t][2] * inv1, co[t][3] * inv1));
    }
}

extern "C" void kernel_launch(void *const *d_in, const int *in_sizes, int n_in,
                              void *d_out, int out_size) {
    const float *q = (const float *)d_in[0];
    const float *k = (const float *)d_in[1];
    const float *v = (const float *)d_in[2];
    rpe_mlp_kernel<<<1, 256>>>((const float *)d_in[5], (const float *)d_in[6],
                               (const float *)d_in[7], (const float *)d_in[8],
                               (const float *)d_in[9], (const float *)d_in[10],
                               (const float *)d_in[11], (const float *)d_in[12],
                               (const float *)d_in[13], (const float *)d_in[14],
                               (const float *)d_in[15], (const float *)d_in[16],
                               (const float *)d_in[17], (const float *)d_in[18]);

    // attn with Programmatic Dependent Launch: overlaps its load phase with rpe.
    cudaLaunchConfig_t cfg = {};
    cfg.gridDim = dim3(24576, 1, 1);
    cfg.blockDim = dim3(128, 1, 1);
    cfg.dynamicSmemBytes = 0;
    cfg.stream = 0;
    cudaLaunchAttribute attr[1];
    attr[0].id = cudaLaunchAttributeProgrammaticStreamSerialization;
    attr[0].val.programmaticStreamSerializationAllowed = 1;
    cfg.attrs = attr;
    cfg.numAttrs = 1;
    cudaLaunchKernelEx(&cfg, attn_kernel, q, k, v, (float *)d_out);
}